// round 16
// baseline (speedup 1.0000x reference)
#include <cuda_runtime.h>
#include <cstdint>

#define NCH   30                  // channels per cell
#define TILE  56                  // cells per pipeline stage
#define THR   128                 // threads per CTA
#define STAGE_F (TILE * NCH * 2)  // floats per stage = 3360
#define STAGE_B (STAGE_F * 4)     // bytes per stage  = 13440
#define HALF_B  (STAGE_B / 2)     // 6720 (16B-aligned)
#define GRID  1024                // 14336 tiles / 1024 = exactly 14 per CTA

__device__ float g_partials[2048];
__device__ unsigned int g_count;   // zeroed at load; reset by last CTA

__device__ __forceinline__ void bulk_g2s(uint32_t dst, const void* src,
                                         uint32_t bytes, uint32_t bar) {
    asm volatile(
        "cp.async.bulk.shared::cluster.global.mbarrier::complete_tx::bytes "
        "[%0], [%1], %2, [%3];"
        :: "r"(dst), "l"(src), "r"(bytes), "r"(bar) : "memory");
}
__device__ __forceinline__ void mbar_init(uint32_t bar, uint32_t cnt) {
    asm volatile("mbarrier.init.shared.b64 [%0], %1;" :: "r"(bar), "r"(cnt) : "memory");
}
__device__ __forceinline__ void mbar_expect_tx(uint32_t bar, uint32_t bytes) {
    asm volatile("mbarrier.arrive.expect_tx.shared.b64 _, [%0], %1;"
                 :: "r"(bar), "r"(bytes) : "memory");
}
__device__ __forceinline__ void mbar_wait(uint32_t bar, uint32_t parity) {
    asm volatile(
        "{\n\t.reg .pred P;\n\t"
        "WL_%=:\n\t"
        "mbarrier.try_wait.parity.acquire.cta.shared::cta.b64 P, [%0], %1, 0x989680;\n\t"
        "@P bra.uni WD_%=;\n\t"
        "bra.uni WL_%=;\n\t"
        "WD_%=:\n\t}"
        :: "r"(bar), "r"(parity) : "memory");
}

// issue both halves of a tile into stage smem, completing on bar
__device__ __forceinline__ void issue_tile(uint32_t sdst, const float* pred,
                                           const float* target, int tile,
                                           uint32_t bar) {
    mbar_expect_tx(bar, STAGE_B);
    const char* ps = (const char*)pred   + (size_t)tile * HALF_B;
    const char* ts = (const char*)target + (size_t)tile * HALF_B;
    bulk_g2s(sdst,          ps, HALF_B, bar);
    bulk_g2s(sdst + HALF_B, ts, HALF_B, bar);
}

__global__ void __launch_bounds__(THR) yolo_loss_bulk(
    const float* __restrict__ pred, const float* __restrict__ target,
    int ntiles, float invN, float* __restrict__ out)
{
    __shared__ __align__(1024) float buf[2 * STAGE_F];   // 26880 B
    __shared__ __align__(8) unsigned long long mbar[2];
    __shared__ float warpsum[4];
    __shared__ unsigned int s_rank;

    const int tid = threadIdx.x;
    const uint32_t sm0  = (uint32_t)__cvta_generic_to_shared(buf);
    const uint32_t bar0 = (uint32_t)__cvta_generic_to_shared(mbar);
    const float STEP = 1.0f / 7.0f;

    const int bx = blockIdx.x;
    const int my_n = (ntiles - bx + GRID - 1) / GRID;   // = 14 for all CTAs
    float acc = 0.0f;                          // per-thread accumulator
    int ph0 = 0, ph1 = 0;                      // per-stage phase parity

    // hoisted grid coords: TILE*GRID mod 49 == 14 -> gx invariant, gy += 2 (mod 7)
    const int lc = (tid < TILE) ? tid : (tid - 64);
    int c49 = ((bx * TILE) + lc) % 49;
    const float gx = (float)(c49 % 7);
    int gyi = c49 / 7;

    if (tid == 0) {
        mbar_init(bar0, 1);
        mbar_init(bar0 + 8, 1);
    }
    __syncthreads();

    if (tid == 0 && my_n > 0)
        issue_tile(sm0, pred, target, bx, bar0);   // prologue -> stage 0

    for (int it = 0; it < my_n; ++it) {
        const int tile = bx + it * GRID;
        const int s = it & 1;

        // KEY REORDER vs R12: prove stage (it+1)&1 free via the barrier
        // everyone must pass anyway, and issue tile it+1 BEFORE waiting on
        // tile it's arrival -> two TMA requests in flight per CTA.
        __syncthreads();                       // stage it-1 consumed by all
        if (tid == 0 && it + 1 < my_n)
            issue_tile(sm0 + ((it + 1) & 1) * STAGE_B, pred, target,
                       tile + GRID, bar0 + ((it + 1) & 1) * 8);

        if (s == 0) { mbar_wait(bar0,     ph0); ph0 ^= 1; }
        else        { mbar_wait(bar0 + 8, ph1); ph1 ^= 1; }

        const float* S = buf + s * STAGE_F;
        const float gy = (float)gyi;

        if (tid < TILE) {
            // ---- warps 0-1: box/conf/IoU losses for cell tid ----
            const float* P = S + tid * NCH;
            const float* T = S + TILE * NCH + tid * NCH;
            const float mask = (T[9] > 0.0f) ? 1.0f : 0.0f;

            float iou[2];
            #pragma unroll
            for (int b = 0; b < 2; ++b) {
                const float* pb = P + 5 * b;
                const float* tb = T + 5 * b;
                float pw = fmaxf(pb[2], 0.0f), ph = fmaxf(pb[3], 0.0f);
                float px = fmaxf((pb[0] + gx) * STEP - pb[2] * 0.5f, 0.0f);
                float py = fmaxf((pb[1] + gy) * STEP - pb[3] * 0.5f, 0.0f);
                float tw = fmaxf(tb[2], 0.0f), th = fmaxf(tb[3], 0.0f);
                float tx = fmaxf((tb[0] + gx) * STEP - tb[2] * 0.5f, 0.0f);
                float ty = fmaxf((tb[1] + gy) * STEP - tb[3] * 0.5f, 0.0f);
                float iw = fmaxf(pw + tw - (fmaxf(px + pw, tx + tw) - fminf(px, tx)), 0.0f);
                float ih = fmaxf(ph + th - (fmaxf(py + ph, ty + th) - fminf(py, ty)), 0.0f);
                float inter = iw * ih;
                float uni = pw * ph + tw * th - inter;
                iou[b] = inter / (uni + 1e-10f);
            }
            const int resp = (iou[1] > iou[0]) ? 1 : 0;

            #pragma unroll
            for (int b = 0; b < 2; ++b) {
                const float ob = (b == resp) ? mask : 0.0f;
                const float* pb = P + 5 * b;
                const float* tb = T + 5 * b;
                float d0 = pb[0] - tb[0], d1 = pb[1] - tb[1];
                float d2 = pb[2] - tb[2], d3 = pb[3] - tb[3];
                acc += 5.0f * ob * (d0 * d0 + d1 * d1 + d2 * d2 + d3 * d3);
                float cf = pb[4];
                float dc = cf - iou[b];
                acc += ob * dc * dc + 0.5f * (1.0f - ob) * cf * cf;
            }
        } else if (tid >= 64 && tid < 64 + TILE) {
            // ---- warps 2-3: class loss for cell (tid-64) ----
            const float* P = S + lc * NCH;
            const float* T = S + TILE * NCH + lc * NCH;
            const float mask = (T[9] > 0.0f) ? 1.0f : 0.0f;
            float cls = 0.0f;
            #pragma unroll
            for (int k = 10; k < 30; ++k) {
                float d = P[k] - T[k];
                cls += d * d;
            }
            acc += mask * cls;
        }

        gyi += 2; if (gyi >= 7) gyi -= 7;      // advance 2 rows (mod 7)
    }

    // ---- single end-of-kernel block reduction ----
    #pragma unroll
    for (int o = 16; o; o >>= 1)
        acc += __shfl_down_sync(0xffffffffu, acc, o);
    if ((tid & 31) == 0) warpsum[tid >> 5] = acc;
    __syncthreads();

    if (tid == 0) {
        float s = (warpsum[0] + warpsum[1]) + (warpsum[2] + warpsum[3]);
        __stcg(&g_partials[bx], s);
        unsigned int rank;
        asm volatile("atom.acq_rel.gpu.global.add.u32 %0, [%1], %2;"
                     : "=r"(rank) : "l"(&g_count), "r"(1u) : "memory");
        s_rank = rank;
    }
    __syncthreads();

    // ---- last CTA folds all partials in fixed order ----
    if (s_rank == GRID - 1) {
        float s = 0.0f;
        for (int i = tid; i < GRID; i += THR)
            s += __ldcg(&g_partials[i]);
        #pragma unroll
        for (int o = 16; o; o >>= 1)
            s += __shfl_down_sync(0xffffffffu, s, o);
        __shared__ float fin[THR / 32];
        if ((tid & 31) == 0) fin[tid >> 5] = s;
        __syncthreads();
        if (tid == 0) {
            float tot = (fin[0] + fin[1]) + (fin[2] + fin[3]);
            out[0] = tot * invN;
            g_count = 0;                        // reset for graph replay
        }
    }
}

extern "C" void kernel_launch(void* const* d_in, const int* in_sizes, int n_in,
                              void* d_out, int out_size)
{
    const float* pred   = (const float*)d_in[0];
    const float* target = (const float*)d_in[1];
    const int total  = in_sizes[0];           // N*49*30
    const int ncells = total / NCH;           // 802816
    const int ntiles = ncells / TILE;         // 14336 (exact)
    const float invN = 1.0f / (float)(ncells / 49);

    yolo_loss_bulk<<<GRID, THR>>>(pred, target, ntiles, invN, (float*)d_out);
}

// round 17
// speedup vs baseline: 1.0652x; 1.0652x over previous
#include <cuda_runtime.h>
#include <cstdint>

#define NCH   30                  // channels per cell
#define TILE  56                  // cells per pipeline stage
#define THR   128                 // threads per CTA
#define STAGE_F (TILE * NCH * 2)  // floats per stage = 3360
#define STAGE_B (STAGE_F * 4)     // bytes per stage  = 13440
#define HALF_B  (STAGE_B / 2)     // 6720 (16B-aligned)
#define GRID  1024                // 14336 tiles / 1024 = exactly 14 per CTA

__device__ float g_partials[2048];
__device__ unsigned int g_count;   // zeroed at load; reset by last CTA

__device__ __forceinline__ void bulk_g2s(uint32_t dst, const void* src,
                                         uint32_t bytes, uint32_t bar) {
    asm volatile(
        "cp.async.bulk.shared::cluster.global.mbarrier::complete_tx::bytes "
        "[%0], [%1], %2, [%3];"
        :: "r"(dst), "l"(src), "r"(bytes), "r"(bar) : "memory");
}
__device__ __forceinline__ void mbar_init(uint32_t bar, uint32_t cnt) {
    asm volatile("mbarrier.init.shared.b64 [%0], %1;" :: "r"(bar), "r"(cnt) : "memory");
}
__device__ __forceinline__ void mbar_expect_tx(uint32_t bar, uint32_t bytes) {
    asm volatile("mbarrier.arrive.expect_tx.shared.b64 _, [%0], %1;"
                 :: "r"(bar), "r"(bytes) : "memory");
}
__device__ __forceinline__ void mbar_wait(uint32_t bar, uint32_t parity) {
    asm volatile(
        "{\n\t.reg .pred P;\n\t"
        "WL_%=:\n\t"
        "mbarrier.try_wait.parity.acquire.cta.shared::cta.b64 P, [%0], %1, 0x989680;\n\t"
        "@P bra.uni WD_%=;\n\t"
        "bra.uni WL_%=;\n\t"
        "WD_%=:\n\t}"
        :: "r"(bar), "r"(parity) : "memory");
}

// issue both halves of a tile into stage smem, completing on bar
__device__ __forceinline__ void issue_tile(uint32_t sdst, const float* pred,
                                           const float* target, int tile,
                                           uint32_t bar) {
    mbar_expect_tx(bar, STAGE_B);
    const char* ps = (const char*)pred   + (size_t)tile * HALF_B;
    const char* ts = (const char*)target + (size_t)tile * HALF_B;
    bulk_g2s(sdst,          ps, HALF_B, bar);
    bulk_g2s(sdst + HALF_B, ts, HALF_B, bar);
}

__global__ void __launch_bounds__(THR) yolo_loss_bulk(
    const float* __restrict__ pred, const float* __restrict__ target,
    int ntiles, float invN, float* __restrict__ out)
{
    __shared__ __align__(1024) float buf[2 * STAGE_F];   // 26880 B
    __shared__ __align__(8) unsigned long long mbar[2];
    __shared__ float warpsum[4];
    __shared__ unsigned int s_rank;

    const int tid = threadIdx.x;
    const uint32_t sm0  = (uint32_t)__cvta_generic_to_shared(buf);
    const uint32_t bar0 = (uint32_t)__cvta_generic_to_shared(mbar);
    const float STEP = 1.0f / 7.0f;

    const int bx = blockIdx.x;
    const int my_n = (ntiles - bx + GRID - 1) / GRID;   // = 14 for all CTAs
    float acc = 0.0f;                          // per-thread accumulator
    int ph0 = 0, ph1 = 0;                      // per-stage phase parity

    // hoisted grid coords: TILE*GRID mod 49 == 14 -> gx invariant, gy += 2 (mod 7)
    const int lc = (tid < TILE) ? tid : (tid - 64);
    int c49 = ((bx * TILE) + lc) % 49;
    const float gx = (float)(c49 % 7);
    int gyi = c49 / 7;

    if (tid == 0) {
        mbar_init(bar0, 1);
        mbar_init(bar0 + 8, 1);
    }
    __syncthreads();

    if (tid == 0 && my_n > 0)
        issue_tile(sm0, pred, target, bx, bar0);   // prologue -> stage 0

    for (int it = 0; it < my_n; ++it) {
        const int tile = bx + it * GRID;
        const int s = it & 1;
        if (s == 0) { mbar_wait(bar0,     ph0); ph0 ^= 1; }
        else        { mbar_wait(bar0 + 8, ph1); ph1 ^= 1; }
        __syncthreads();                       // all done with stage it-1

        if (tid == 0 && it + 1 < my_n)         // refill freed stage
            issue_tile(sm0 + ((it + 1) & 1) * STAGE_B, pred, target,
                       tile + GRID, bar0 + ((it + 1) & 1) * 8);

        const float* S = buf + s * STAGE_F;
        const float gy = (float)gyi;

        if (tid < TILE) {
            // ---- warps 0-1: box/conf/IoU losses for cell tid ----
            const float* P = S + tid * NCH;
            const float* T = S + TILE * NCH + tid * NCH;
            const float mask = (T[9] > 0.0f) ? 1.0f : 0.0f;

            float iou[2];
            #pragma unroll
            for (int b = 0; b < 2; ++b) {
                const float* pb = P + 5 * b;
                const float* tb = T + 5 * b;
                float pw = fmaxf(pb[2], 0.0f), ph = fmaxf(pb[3], 0.0f);
                float px = fmaxf((pb[0] + gx) * STEP - pb[2] * 0.5f, 0.0f);
                float py = fmaxf((pb[1] + gy) * STEP - pb[3] * 0.5f, 0.0f);
                float tw = fmaxf(tb[2], 0.0f), th = fmaxf(tb[3], 0.0f);
                float tx = fmaxf((tb[0] + gx) * STEP - tb[2] * 0.5f, 0.0f);
                float ty = fmaxf((tb[1] + gy) * STEP - tb[3] * 0.5f, 0.0f);
                float iw = fmaxf(pw + tw - (fmaxf(px + pw, tx + tw) - fminf(px, tx)), 0.0f);
                float ih = fmaxf(ph + th - (fmaxf(py + ph, ty + th) - fminf(py, ty)), 0.0f);
                float inter = iw * ih;
                float uni = pw * ph + tw * th - inter;
                iou[b] = inter / (uni + 1e-10f);
            }
            const int resp = (iou[1] > iou[0]) ? 1 : 0;

            #pragma unroll
            for (int b = 0; b < 2; ++b) {
                const float ob = (b == resp) ? mask : 0.0f;
                const float* pb = P + 5 * b;
                const float* tb = T + 5 * b;
                float d0 = pb[0] - tb[0], d1 = pb[1] - tb[1];
                float d2 = pb[2] - tb[2], d3 = pb[3] - tb[3];
                acc += 5.0f * ob * (d0 * d0 + d1 * d1 + d2 * d2 + d3 * d3);
                float cf = pb[4];
                float dc = cf - iou[b];
                acc += ob * dc * dc + 0.5f * (1.0f - ob) * cf * cf;
            }
        } else if (tid >= 64 && tid < 64 + TILE) {
            // ---- warps 2-3: class loss for cell (tid-64) ----
            const float* P = S + lc * NCH;
            const float* T = S + TILE * NCH + lc * NCH;
            const float mask = (T[9] > 0.0f) ? 1.0f : 0.0f;
            float cls = 0.0f;
            #pragma unroll
            for (int k = 10; k < 30; ++k) {
                float d = P[k] - T[k];
                cls += d * d;
            }
            acc += mask * cls;
        }

        gyi += 2; if (gyi >= 7) gyi -= 7;      // advance 2 rows (mod 7)
        // no trailing sync: next iter's post-wait __syncthreads guards reuse
    }

    // ---- single end-of-kernel block reduction ----
    #pragma unroll
    for (int o = 16; o; o >>= 1)
        acc += __shfl_down_sync(0xffffffffu, acc, o);
    if ((tid & 31) == 0) warpsum[tid >> 5] = acc;
    __syncthreads();

    if (tid == 0) {
        float s = (warpsum[0] + warpsum[1]) + (warpsum[2] + warpsum[3]);
        __stcg(&g_partials[bx], s);
        unsigned int rank;
        asm volatile("atom.acq_rel.gpu.global.add.u32 %0, [%1], %2;"
                     : "=r"(rank) : "l"(&g_count), "r"(1u) : "memory");
        s_rank = rank;
    }
    __syncthreads();

    // ---- last CTA folds all partials in fixed order ----
    if (s_rank == GRID - 1) {
        float s = 0.0f;
        for (int i = tid; i < GRID; i += THR)
            s += __ldcg(&g_partials[i]);
        #pragma unroll
        for (int o = 16; o; o >>= 1)
            s += __shfl_down_sync(0xffffffffu, s, o);
        __shared__ float fin[THR / 32];
        if ((tid & 31) == 0) fin[tid >> 5] = s;
        __syncthreads();
        if (tid == 0) {
            float tot = (fin[0] + fin[1]) + (fin[2] + fin[3]);
            out[0] = tot * invN;
            g_count = 0;                        // reset for graph replay
        }
    }
}

extern "C" void kernel_launch(void* const* d_in, const int* in_sizes, int n_in,
                              void* d_out, int out_size)
{
    const float* pred   = (const float*)d_in[0];
    const float* target = (const float*)d_in[1];
    const int total  = in_sizes[0];           // N*49*30
    const int ncells = total / NCH;           // 802816
    const int ntiles = ncells / TILE;         // 14336 (exact)
    const float invN = 1.0f / (float)(ncells / 49);

    yolo_loss_bulk<<<GRID, THR>>>(pred, target, ntiles, invN, (float*)d_out);
}